// round 15
// baseline (speedup 1.0000x reference)
#include <cuda_runtime.h>
#include <cuda_bf16.h>

// Problem constants (HiePoolingLayer): nn_outs (B,T,E) f32, batch_x (B,T) int
#define B 32
#define T 4096
#define E 256
#define E4 (E / 4)   // 64 float4 lanes per token row

// __device__ scratch (no dynamic allocation allowed)
__device__ int g_cut_pos[B][T];     // token index of k-th cut in row b
__device__ int g_ncuts[B];          // number of cuts (segments) in row b
__device__ int g_row_uniform[B];    // 1 if row's cuts are exactly 15,31,...

// ---------------------------------------------------------------------------
// Kernel 1 (prep): dtype detect + cut scan + ncuts + uniform flag + tail.
// One block per row, 256 threads x 16 tokens each. (Proven version.)
// Detection (globally consistent): int32 layout has cuts at odd word indices;
// int64 layout's odd words (hi halves of 0/1) are all zero.
// ---------------------------------------------------------------------------
__global__ __launch_bounds__(256) void prep_kernel(const int* __restrict__ bx32,
                                                   float* __restrict__ out,
                                                   long long tail_off,
                                                   int tail_mode) {
    const int b    = blockIdx.x;
    const int tid  = threadIdx.x;
    const int base = tid * 16;

    // vectorized probe load: 16 words at [b*T + tid*16] (4 x LDG.128)
    int v[16];
    const int4* slice4 = (const int4*)(bx32 + (size_t)b * T) + tid * 4;
    int4 w0 = slice4[0], w1 = slice4[1], w2 = slice4[2], w3 = slice4[3];
    v[0]=w0.x; v[1]=w0.y; v[2]=w0.z; v[3]=w0.w;
    v[4]=w1.x; v[5]=w1.y; v[6]=w1.z; v[7]=w1.w;
    v[8]=w2.x; v[9]=w2.y; v[10]=w2.z; v[11]=w2.w;
    v[12]=w3.x; v[13]=w3.y; v[14]=w3.z; v[15]=w3.w;

    int odd_any = 0;
#pragma unroll
    for (int i = 1; i < 16; i += 2) odd_any |= v[i];
    const int is32 = __syncthreads_or(odd_any != 0);

    unsigned mask = 0;
    int cnt = 0;
    if (is32) {
#pragma unroll
        for (int i = 0; i < 16; i++) {
            if (v[i] == 1) { mask |= (1u << i); cnt++; }
        }
    } else {
        // int64 layout: row b at words [b*2T, b*2T+2T); token j = words 2j,2j+1
        const int* row64 = bx32 + (size_t)b * T * 2;
#pragma unroll
        for (int i = 0; i < 16; i++) {
            if (row64[2 * (base + i)] == 1 && row64[2 * (base + i) + 1] == 0) {
                mask |= (1u << i); cnt++;
            }
        }
    }

    // uniform: every 16-token chunk has exactly one cut at local offset 15
    const int uniform = __syncthreads_and(mask == 0x8000u);

    // warp inclusive scan of cnt
    const int lane = tid & 31;
    const int wid  = tid >> 5;
    int x = cnt;
#pragma unroll
    for (int o = 1; o < 32; o <<= 1) {
        int y = __shfl_up_sync(0xFFFFFFFFu, x, o);
        if (lane >= o) x += y;
    }

    __shared__ int wsum[8];
    if (lane == 31) wsum[wid] = x;
    __syncthreads();

    int wexcl = 0;
    for (int i = 0; i < wid; i++) wexcl += wsum[i];

    const int excl = wexcl + x - cnt;   // rank of my first cut

    int r = excl;
#pragma unroll
    for (int i = 0; i < 16; i++) {
        if ((mask >> i) & 1u) {
            g_cut_pos[b][r++] = base + i;
        }
    }

    if (tid == blockDim.x - 1) {
        const int total = excl + cnt;
        g_ncuts[b] = total;
        g_row_uniform[b] = uniform;     // unconditional write: replay-safe
        if (tail_mode == 1) {
            out[tail_off + b] = (float)total;           // f32 output dtype
        } else if (tail_mode == 2) {
            ((long long*)out)[tail_off / 2 + b] = (long long)total;  // i64
        }
    }
    __syncthreads();
    // Resolve the dependent (PDL) pool launch as soon as scratch is written.
    cudaTriggerProgrammaticLaunchCompletion();
}

// ---------------------------------------------------------------------------
// Kernel 2: pool. 256-thread blocks = FOUR independent 64-lane groups, one
// segment each (grid = nseg/4). Per-group code identical to the proven
// fastest shape. PDL + speculation: groups speculatively sum assuming
// uniform stride-16 (nn loads always in-bounds), wait on prep, commit or
// recompute.
// ---------------------------------------------------------------------------
__global__ __launch_bounds__(256) void pool_kernel(const float* __restrict__ nn,
                                                   float* __restrict__ out,
                                                   int maxlen) {
    const int grp  = blockIdx.x * 4 + (threadIdx.x >> 6);
    const int lane = threadIdx.x & 63;
    const int nseg = B * maxlen;

    const int flat  = grp;
    const int valid = (flat < nseg);
    const int b     = valid ? flat / maxlen : 0;
    const int seg   = valid ? flat % maxlen : 0;

    // ---- speculative sum (overlaps prep via PDL early launch) ----
    float4 spec = make_float4(0.f, 0.f, 0.f, 0.f);
    const int can_spec = valid && (seg < T / 16);
    if (can_spec) {
        const float4* src =
            (const float4*)nn + ((size_t)b * T + (seg << 4)) * E4 + lane;
#pragma unroll
        for (int t = 0; t < 16; t++) {
            float4 v = src[(size_t)t * E4];
            spec.x += v.x; spec.y += v.y; spec.z += v.z; spec.w += v.w;
        }
        spec.x *= 0.0625f; spec.y *= 0.0625f;
        spec.z *= 0.0625f; spec.w *= 0.0625f;
    }

    cudaGridDependencySynchronize();   // prep results now visible
    if (!valid) return;

    float4* o = (float4*)out + (size_t)flat * E4 + lane;

    const int nc = g_ncuts[b];
    if (seg >= nc) {
        *o = make_float4(0.f, 0.f, 0.f, 0.f);   // pad segment -> zeros
        return;
    }

    if (g_row_uniform[b] && can_spec) {
        *o = spec;                               // commit speculation
        return;
    }

    // generic path: arbitrary cut positions
    const int end   = g_cut_pos[b][seg];                    // inclusive
    const int start = (seg > 0) ? (g_cut_pos[b][seg - 1] + 1) : 0;
    const int len   = end - start + 1;

    const float4* src = (const float4*)nn + ((size_t)b * T + start) * E4 + lane;
    float4 acc = make_float4(0.f, 0.f, 0.f, 0.f);
#pragma unroll 4
    for (int t = 0; t < len; t++) {
        float4 v = src[(size_t)t * E4];
        acc.x += v.x; acc.y += v.y; acc.z += v.z; acc.w += v.w;
    }
    const float inv = 1.0f / (float)len;
    acc.x *= inv; acc.y *= inv; acc.z *= inv; acc.w *= inv;
    *o = acc;
}

extern "C" void kernel_launch(void* const* d_in, const int* in_sizes, int n_in,
                              void* d_out, int out_size) {
    // Defensive input-order check: nn_outs has B*T*E elements, batch_x B*T.
    int i_nn = 0, i_bx = 1;
    if (n_in >= 2 && in_sizes[0] == B * T && in_sizes[1] != B * T) {
        i_nn = 1; i_bx = 0;
    }
    const float* nn   = (const float*)d_in[i_nn];    // (B,T,E) f32
    const int*   bx32 = (const int*)d_in[i_bx];      // (B,T) i32 or i64 view
    float*       out  = (float*)d_out;

    // Derive maxlen (and optional n_cuts tail) from out_size.
    const long long bE = (long long)B * E;
    int maxlen = 0;
    int tail_mode = 0;  // 0=none, 1=B output-dtype elems (float), 2=i64 tail
    if (out_size % bE == 0) {
        maxlen = (int)(out_size / bE);
    } else if ((out_size - B) % bE == 0) {
        maxlen = (int)((out_size - B) / bE);
        tail_mode = 1;
    } else if ((out_size - 2 * B) % bE == 0) {
        maxlen = (int)((out_size - 2 * B) / bE);
        tail_mode = 2;
    } else {
        maxlen = T / 16;  // fallback: uniform stride-16 cuts
    }

    const long long tail_off = (long long)B * maxlen * E;

    prep_kernel<<<B, 256>>>(bx32, out, tail_off, tail_mode);

    // PDL launch: pool blocks roll out and run speculative loads during prep.
    const int nseg    = B * maxlen;
    const int nblocks = (nseg + 3) / 4;            // 4 segments per block
    cudaLaunchConfig_t cfg = {};
    cfg.gridDim  = dim3((unsigned)nblocks, 1, 1);
    cfg.blockDim = dim3(256, 1, 1);
    cfg.dynamicSmemBytes = 0;
    cfg.stream = 0;
    cudaLaunchAttribute attrs[1];
    attrs[0].id = cudaLaunchAttributeProgrammaticStreamSerialization;
    attrs[0].val.programmaticStreamSerializationAllowed = 1;
    cfg.attrs = attrs;
    cfg.numAttrs = 1;
    cudaError_t err = cudaLaunchKernelEx(&cfg, pool_kernel, nn, out, maxlen);
    if (err != cudaSuccess) {
        // Fallback: plain launch (still correct, just serialized).
        pool_kernel<<<nblocks, 256>>>(nn, out, maxlen);
    }
}

// round 16
// speedup vs baseline: 1.0837x; 1.0837x over previous
#include <cuda_runtime.h>
#include <cuda_bf16.h>

// Problem constants (HiePoolingLayer): nn_outs (B,T,E) f32, batch_x (B,T) int
#define B 32
#define T 4096
#define E 256
#define E4 (E / 4)   // 64 float4 lanes per token row

// __device__ scratch (no dynamic allocation allowed)
__device__ int g_cut_pos[B][T];     // token index of k-th cut in row b

// ---------------------------------------------------------------------------
// Kernel 1 (pool guess, NO dependencies): each 64-lane group writes the
// uniform-stride-16 answer for its segment: mean of tokens [seg*16, seg*16+15]
// for seg < T/16, zeros beyond (pad guess). Starts streaming at t=0.
// ---------------------------------------------------------------------------
__global__ __launch_bounds__(128) void pool_guess_kernel(
        const float* __restrict__ nn, float* __restrict__ out, int maxlen) {
    const int grp  = blockIdx.x * 2 + (threadIdx.x >> 6);
    const int lane = threadIdx.x & 63;
    const int nseg = B * maxlen;
    if (grp >= nseg) return;

    const int b   = grp / maxlen;
    const int seg = grp % maxlen;

    float4* o = (float4*)out + (size_t)grp * E4 + lane;

    if (seg < T / 16) {
        const float4* src =
            (const float4*)nn + ((size_t)b * T + (seg << 4)) * E4 + lane;
        float4 acc = make_float4(0.f, 0.f, 0.f, 0.f);
#pragma unroll
        for (int t = 0; t < 16; t++) {
            float4 v = src[(size_t)t * E4];
            acc.x += v.x; acc.y += v.y; acc.z += v.z; acc.w += v.w;
        }
        acc.x *= 0.0625f; acc.y *= 0.0625f;
        acc.z *= 0.0625f; acc.w *= 0.0625f;
        *o = acc;
    } else {
        *o = make_float4(0.f, 0.f, 0.f, 0.f);
    }
    cudaTriggerProgrammaticLaunchCompletion();
}

// ---------------------------------------------------------------------------
// Kernel 2 (repair, PDL): one block per row, 256 threads x 16 tokens.
// Phase 1 (overlaps pool's tail): scan flags -> cut_pos/ncuts/uniform.
// Phase 2: grid-dependency sync (pool's writes complete), write n_cuts tail,
// and for NON-uniform rows recompute every segment of the row (one warp per
// segment, lanes cover 2 float4 columns each).
// Dtype detection (globally consistent): int32 layout has cuts at odd word
// indices; int64 layout's odd words (hi halves of 0/1) are all zero.
// ---------------------------------------------------------------------------
__global__ __launch_bounds__(256) void repair_kernel(
        const int* __restrict__ bx32, const float* __restrict__ nn,
        float* __restrict__ out, int maxlen,
        long long tail_off, int tail_mode) {
    const int b    = blockIdx.x;
    const int tid  = threadIdx.x;
    const int base = tid * 16;

    // ---- Phase 1: scan (reads only inputs; overlaps pool via PDL) ----
    int v[16];
    const int4* slice4 = (const int4*)(bx32 + (size_t)b * T) + tid * 4;
    int4 w0 = slice4[0], w1 = slice4[1], w2 = slice4[2], w3 = slice4[3];
    v[0]=w0.x; v[1]=w0.y; v[2]=w0.z; v[3]=w0.w;
    v[4]=w1.x; v[5]=w1.y; v[6]=w1.z; v[7]=w1.w;
    v[8]=w2.x; v[9]=w2.y; v[10]=w2.z; v[11]=w2.w;
    v[12]=w3.x; v[13]=w3.y; v[14]=w3.z; v[15]=w3.w;

    int odd_any = 0;
#pragma unroll
    for (int i = 1; i < 16; i += 2) odd_any |= v[i];
    const int is32 = __syncthreads_or(odd_any != 0);

    unsigned mask = 0;
    int cnt = 0;
    if (is32) {
#pragma unroll
        for (int i = 0; i < 16; i++) {
            if (v[i] == 1) { mask |= (1u << i); cnt++; }
        }
    } else {
        const int* row64 = bx32 + (size_t)b * T * 2;
#pragma unroll
        for (int i = 0; i < 16; i++) {
            if (row64[2 * (base + i)] == 1 && row64[2 * (base + i) + 1] == 0) {
                mask |= (1u << i); cnt++;
            }
        }
    }

    // uniform: every 16-token chunk has exactly one cut at local offset 15
    const int uniform = __syncthreads_and(mask == 0x8000u);

    // inclusive warp scan of cnt, then block combine
    const int lane = tid & 31;
    const int wid  = tid >> 5;
    int x = cnt;
#pragma unroll
    for (int o = 1; o < 32; o <<= 1) {
        int y = __shfl_up_sync(0xFFFFFFFFu, x, o);
        if (lane >= o) x += y;
    }
    __shared__ int wsum[8];
    __shared__ int s_nc;
    if (lane == 31) wsum[wid] = x;
    __syncthreads();
    int wexcl = 0;
    for (int i = 0; i < wid; i++) wexcl += wsum[i];
    const int excl = wexcl + x - cnt;

    int r = excl;
#pragma unroll
    for (int i = 0; i < 16; i++) {
        if ((mask >> i) & 1u) {
            g_cut_pos[b][r++] = base + i;
        }
    }
    if (tid == blockDim.x - 1) s_nc = excl + cnt;
    __syncthreads();                   // cut_pos + s_nc visible block-wide
    const int nc = s_nc;

    // ---- Phase 2: wait for pool's writes, then fix ----
    cudaGridDependencySynchronize();

    if (tid == 0) {
        if (tail_mode == 1) {
            out[tail_off + b] = (float)nc;                    // f32 output
        } else if (tail_mode == 2) {
            ((long long*)out)[tail_off / 2 + b] = (long long)nc;
        }
    }

    if (uniform) return;   // guess was exactly right for this row

    // Non-uniform row: recompute every segment. One warp per segment,
    // each lane covers columns (lane) and (lane+32) as float4.
    for (int seg = wid; seg < maxlen; seg += 8) {
        float4* o0 = (float4*)out + ((size_t)b * maxlen + seg) * E4 + lane;
        float4* o1 = o0 + 32;

        if (seg >= nc) {
            *o0 = make_float4(0.f, 0.f, 0.f, 0.f);
            *o1 = make_float4(0.f, 0.f, 0.f, 0.f);
            continue;
        }

        const int end   = g_cut_pos[b][seg];                  // inclusive
        const int start = (seg > 0) ? (g_cut_pos[b][seg - 1] + 1) : 0;
        const int len   = end - start + 1;

        const float4* src =
            (const float4*)nn + ((size_t)b * T + start) * E4 + lane;
        float4 a0 = make_float4(0.f, 0.f, 0.f, 0.f);
        float4 a1 = make_float4(0.f, 0.f, 0.f, 0.f);
        for (int t = 0; t < len; t++) {
            float4 u = src[(size_t)t * E4];
            float4 w = src[(size_t)t * E4 + 32];
            a0.x += u.x; a0.y += u.y; a0.z += u.z; a0.w += u.w;
            a1.x += w.x; a1.y += w.y; a1.z += w.z; a1.w += w.w;
        }
        const float inv = 1.0f / (float)len;
        a0.x *= inv; a0.y *= inv; a0.z *= inv; a0.w *= inv;
        a1.x *= inv; a1.y *= inv; a1.z *= inv; a1.w *= inv;
        *o0 = a0;
        *o1 = a1;
    }
}

extern "C" void kernel_launch(void* const* d_in, const int* in_sizes, int n_in,
                              void* d_out, int out_size) {
    // Defensive input-order check: nn_outs has B*T*E elements, batch_x B*T.
    int i_nn = 0, i_bx = 1;
    if (n_in >= 2 && in_sizes[0] == B * T && in_sizes[1] != B * T) {
        i_nn = 1; i_bx = 0;
    }
    const float* nn   = (const float*)d_in[i_nn];    // (B,T,E) f32
    const int*   bx32 = (const int*)d_in[i_bx];      // (B,T) i32 or i64 view
    float*       out  = (float*)d_out;

    // Derive maxlen (and optional n_cuts tail) from out_size.
    const long long bE = (long long)B * E;
    int maxlen = 0;
    int tail_mode = 0;  // 0=none, 1=B output-dtype elems (float), 2=i64 tail
    if (out_size % bE == 0) {
        maxlen = (int)(out_size / bE);
    } else if ((out_size - B) % bE == 0) {
        maxlen = (int)((out_size - B) / bE);
        tail_mode = 1;
    } else if ((out_size - 2 * B) % bE == 0) {
        maxlen = (int)((out_size - 2 * B) / bE);
        tail_mode = 2;
    } else {
        maxlen = T / 16;  // fallback: uniform stride-16 cuts
    }

    const long long tail_off = (long long)B * maxlen * E;
    const int nseg    = B * maxlen;
    const int nblocks = (nseg + 1) / 2;        // 2 groups per 128-thread block

    // 1) Optimistic pool: no dependencies, starts streaming immediately.
    pool_guess_kernel<<<nblocks, 128>>>(nn, out, maxlen);

    // 2) Repair (PDL): flag scan overlaps pool's tail; overwrites only
    //    non-uniform rows after the dependency sync.
    cudaLaunchConfig_t cfg = {};
    cfg.gridDim  = dim3(B, 1, 1);
    cfg.blockDim = dim3(256, 1, 1);
    cfg.dynamicSmemBytes = 0;
    cfg.stream = 0;
    cudaLaunchAttribute attrs[1];
    attrs[0].id = cudaLaunchAttributeProgrammaticStreamSerialization;
    attrs[0].val.programmaticStreamSerializationAllowed = 1;
    cfg.attrs = attrs;
    cfg.numAttrs = 1;
    cudaError_t err = cudaLaunchKernelEx(&cfg, repair_kernel,
                                         bx32, nn, out, maxlen,
                                         tail_off, tail_mode);
    if (err != cudaSuccess) {
        // Fallback: plain launch (still correct, just serialized).
        repair_kernel<<<B, 256>>>(bx32, nn, out, maxlen, tail_off, tail_mode);
    }
}